// round 5
// baseline (speedup 1.0000x reference)
#include <cuda_runtime.h>

// argmax over last dim of [16, 512, 32000] fp32 -> [8192] float indices.
// Warp-per-row: 4096 warps x exactly 2 consecutive rows each. Zero block-level
// sync -> reduction bubbles amortize to ~0.1%. 4 independent accumulator
// chains (4 LDG.128 in flight/thread), __ldcs streaming loads.
// (Resubmission of R4 kernel: prior round failed on container acquisition,
// not on the kernel.)

#define N_ROWS   (16 * 512)     // 8192
#define N_COLS   32000
#define N_VEC4   (N_COLS / 4)   // 8000 ; per lane: exactly 250
#define THREADS  512
#define GRID     256            // 256*16 warps = 4096 = N_ROWS/2
#define ROWS_PER_WARP 2

__device__ __forceinline__ float neg_inf() {
    return __int_as_float(0xFF800000);
}

__device__ __forceinline__ void upd(float v, int i, float& bv, int& bi) {
    if (v > bv) { bv = v; bi = i; }          // strict '>' => lowest index on tie
}

__device__ __forceinline__ void merge(float ov, int oi, float& bv, int& bi) {
    if (ov > bv || (ov == bv && oi < bi)) { bv = ov; bi = oi; }
}

__global__ __launch_bounds__(THREADS, 2)
void argmax_rows_kernel(const float* __restrict__ in, float* __restrict__ out) {
    const int lid   = threadIdx.x & 31;
    const int gwarp = (blockIdx.x * (THREADS / 32)) + (threadIdx.x >> 5);

    #pragma unroll
    for (int r = 0; r < ROWS_PER_WARP; r++) {
        const int row = gwarp * ROWS_PER_WARP + r;   // 2 consecutive rows/warp
        const float4* __restrict__ rowp =
            reinterpret_cast<const float4*>(in + (size_t)row * N_COLS);

        // 4 independent chains -> 4 concurrent LDG.128/thread, no serial deps.
        float bv0 = neg_inf(), bv1 = neg_inf(), bv2 = neg_inf(), bv3 = neg_inf();
        int   bi0 = 0, bi1 = 0, bi2 = 0, bi3 = 0;

        // 250 vec4/lane = 62 iterations x 4 chains + 2 tail
        int i = lid;
        for (int j = 0; j < 62; j++, i += 128) {
            float4 v0 = __ldcs(rowp + i);
            float4 v1 = __ldcs(rowp + i + 32);
            float4 v2 = __ldcs(rowp + i + 64);
            float4 v3 = __ldcs(rowp + i + 96);
            int b0 = i << 2, b1 = (i + 32) << 2, b2 = (i + 64) << 2, b3 = (i + 96) << 2;
            upd(v0.x, b0,     bv0, bi0); upd(v0.y, b0 + 1, bv0, bi0);
            upd(v0.z, b0 + 2, bv0, bi0); upd(v0.w, b0 + 3, bv0, bi0);
            upd(v1.x, b1,     bv1, bi1); upd(v1.y, b1 + 1, bv1, bi1);
            upd(v1.z, b1 + 2, bv1, bi1); upd(v1.w, b1 + 3, bv1, bi1);
            upd(v2.x, b2,     bv2, bi2); upd(v2.y, b2 + 1, bv2, bi2);
            upd(v2.z, b2 + 2, bv2, bi2); upd(v2.w, b2 + 3, bv2, bi2);
            upd(v3.x, b3,     bv3, bi3); upd(v3.y, b3 + 1, bv3, bi3);
            upd(v3.z, b3 + 2, bv3, bi3); upd(v3.w, b3 + 3, bv3, bi3);
        }
        {   // tail: iterations 248, 249
            float4 v0 = __ldcs(rowp + i);
            float4 v1 = __ldcs(rowp + i + 32);
            int b0 = i << 2, b1 = (i + 32) << 2;
            upd(v0.x, b0,     bv0, bi0); upd(v0.y, b0 + 1, bv0, bi0);
            upd(v0.z, b0 + 2, bv0, bi0); upd(v0.w, b0 + 3, bv0, bi0);
            upd(v1.x, b1,     bv1, bi1); upd(v1.y, b1 + 1, bv1, bi1);
            upd(v1.z, b1 + 2, bv1, bi1); upd(v1.w, b1 + 3, bv1, bi1);
        }

        // merge chains (disjoint index sets; value/index merge handles ties)
        merge(bv1, bi1, bv0, bi0);
        merge(bv3, bi3, bv2, bi2);
        merge(bv2, bi2, bv0, bi0);

        // warp reduce only — no smem, no block sync
        #pragma unroll
        for (int off = 16; off > 0; off >>= 1) {
            float ov = __shfl_down_sync(0xFFFFFFFFu, bv0, off);
            int   oi = __shfl_down_sync(0xFFFFFFFFu, bi0, off);
            merge(ov, oi, bv0, bi0);
        }

        if (lid == 0) out[row] = (float)bi0;
    }
}

extern "C" void kernel_launch(void* const* d_in, const int* in_sizes, int n_in,
                              void* d_out, int out_size) {
    const float* in  = (const float*)d_in[0];
    float*       out = (float*)d_out;
    argmax_rows_kernel<<<GRID, THREADS>>>(in, out);
}